// round 7
// baseline (speedup 1.0000x reference)
#include <cuda_runtime.h>

#define DT 0.05f
#define NSTEPS 41
#define TPB 128
#define MAXB 4096

typedef unsigned long long u64;

__device__ float g_partials[2 * MAXB];
__device__ unsigned g_count;

// ---------- f32x2 helpers ----------
static __device__ __forceinline__ u64 pk2(float lo, float hi) {
    u64 r; asm("mov.b64 %0, {%1, %2};" : "=l"(r) : "f"(lo), "f"(hi)); return r;
}
static __device__ __forceinline__ void up2(u64 v, float& lo, float& hi) {
    asm("mov.b64 {%0, %1}, %2;" : "=f"(lo), "=f"(hi) : "l"(v));
}
static __device__ __forceinline__ u64 bc2(float x) { return pk2(x, x); }
static __device__ __forceinline__ u64 ffma2(u64 a, u64 b, u64 c) {
    u64 d; asm("fma.rn.f32x2 %0, %1, %2, %3;" : "=l"(d) : "l"(a), "l"(b), "l"(c)); return d;
}
static __device__ __forceinline__ u64 fsub2(u64 a, u64 b) {
    u64 d; asm("sub.rn.f32x2 %0, %1, %2;" : "=l"(d) : "l"(a), "l"(b)); return d;
}
static __device__ __forceinline__ u64 fadd2(u64 a, u64 b) {
    u64 d; asm("add.rn.f32x2 %0, %1, %2;" : "=l"(d) : "l"(a), "l"(b)); return d;
}

// ---------- f16x2 helpers ----------
static __device__ __forceinline__ unsigned hfma2(unsigned a, unsigned b, unsigned c) {
    unsigned d; asm("fma.rn.f16x2 %0, %1, %2, %3;" : "=r"(d) : "r"(a), "r"(b), "r"(c)); return d;
}
static __device__ __forceinline__ unsigned hmul2(unsigned a, unsigned b) {
    unsigned d; asm("mul.rn.f16x2 %0, %1, %2;" : "=r"(d) : "r"(a), "r"(b)); return d;
}
static __device__ __forceinline__ unsigned hadd2(unsigned a, unsigned b) {
    unsigned d; asm("add.rn.f16x2 %0, %1, %2;" : "=r"(d) : "r"(a), "r"(b)); return d;
}
static __device__ __forceinline__ unsigned htanh2(unsigned x) {
    asm("tanh.approx.f16x2 %0, %0;" : "+r"(x)); return x;
}
static __device__ __forceinline__ unsigned hsetgt2(unsigned a, unsigned b) {
    unsigned d; asm("set.gt.f16x2.f16x2 %0, %1, %2;" : "=r"(d) : "r"(a), "r"(b)); return d;
}
static __device__ __forceinline__ unsigned bch(float x) {
    unsigned r; asm("cvt.rn.f16x2.f32 %0, %1, %1;" : "=r"(r) : "f"(x)); return r;
}
static __device__ __forceinline__ unsigned cvt_f16x2(u64 x) {
    float lo, hi; up2(x, lo, hi);
    unsigned r; asm("cvt.rn.f16x2.f32 %0, %1, %2;" : "=r"(r) : "f"(hi), "f"(lo));
    return r;
}
static __device__ __forceinline__ void cvt_f32p(unsigned h, float& lo, float& hi) {
    asm("{\n\t.reg .b16 l, hh;\n\tmov.b32 {l, hh}, %2;\n\t"
        "cvt.f32.f16 %0, l;\n\tcvt.f32.f16 %1, hh;\n\t}"
        : "=f"(lo), "=f"(hi) : "r"(h));
}

struct PairState {
    u64 t0, t1, s0, s1, err0, err1, nor;
    unsigned eff16;
    unsigned hb16[4];
};

__global__ void __launch_bounds__(TPB, 4) conv_fused_kernel(
    const float* __restrict__ omega,
    const float* __restrict__ Wh1, const float* __restrict__ bh1,
    const float* __restrict__ Wh2, const float* __restrict__ bh2,
    const float* __restrict__ Wr1, const float* __restrict__ br1,
    const float* __restrict__ Wr2, const float* __restrict__ br2,
    const float* __restrict__ alpha, float* __restrict__ out,
    int N, int half, int nblocks)
{
    // ---- hoisted weights ----
    unsigned wh1s[8], wh2h[4], wr2h[3], bh2h, c001h;
    #pragma unroll
    for (int j = 0; j < 4; j++) {
        wh1s[2 * j + 0] = bch(__ldg(&Wh1[4 * j + 2]));   // s0 column
        wh1s[2 * j + 1] = bch(__ldg(&Wh1[4 * j + 3]));   // s1 column
        wh2h[j] = bch(__ldg(&Wh2[j]));
    }
    #pragma unroll
    for (int j = 0; j < 3; j++) wr2h[j] = bch(__ldg(&Wr2[j]));
    bh2h  = bch(__ldg(&bh2[0]));
    c001h = bch(0.01f);

    u64 wr1p[9], br1p[3];
    #pragma unroll
    for (int j = 0; j < 9; j++) wr1p[j] = bc2(__ldg(&Wr1[j]));
    #pragma unroll
    for (int j = 0; j < 3; j++) br1p[j] = bc2(__ldg(&br1[j]));
    const u64 br2p = bc2(__ldg(&br2[0]));
    const u64 cP1 = bc2(0.1f);
    const u64 cDT = bc2(DT);

    float csum = 0.0f, nsum = 0.0f;
    const int idx = blockIdx.x * TPB + threadIdx.x;

    if (idx < half) {
        // ---- init both pairs (weights used here die before the main loop) ----
        PairState P[2];
        #pragma unroll
        for (int q = 0; q < 2; q++) {
            const int p = idx + q * half;
            const float2 t0v = *(const float2*)(omega + 2 * p);
            const float2 t1v = *(const float2*)(omega + N + 2 * p);
            P[q].t0 = pk2(t0v.x, t0v.y);
            P[q].t1 = pk2(t1v.x, t1v.y);
            #pragma unroll
            for (int j = 0; j < 4; j++) {
                u64 hb = ffma2(bc2(__ldg(&Wh1[4 * j + 1])), P[q].t1,
                        ffma2(bc2(__ldg(&Wh1[4 * j + 0])), P[q].t0,
                              bc2(__ldg(&bh1[j]))));
                P[q].hb16[j] = cvt_f16x2(hb);
            }
            P[q].s0 = 0ull; P[q].s1 = 0ull;
            P[q].err0 = 0ull; P[q].err1 = 0ull; P[q].nor = 0ull;
            P[q].eff16 = 0u;
        }

        auto body = [&](PairState& S) {
            const u64 e0 = fsub2(S.t0, S.s0);
            const u64 e1 = fsub2(S.t1, S.s1);
            S.err0 = ffma2(e0, e0, S.err0);        // x10 folded at the end
            S.err1 = ffma2(e1, e1, S.err1);
            const u64 zt = ffma2(cP1, e1, e0);

            // human MLP: fully f16x2
            const unsigned s0h = cvt_f16x2(S.s0);
            const unsigned s1h = cvt_f16x2(S.s1);
            const unsigned h0 = htanh2(hfma2(wh1s[1], s1h, hfma2(wh1s[0], s0h, S.hb16[0])));
            const unsigned h1 = htanh2(hfma2(wh1s[3], s1h, hfma2(wh1s[2], s0h, S.hb16[1])));
            const unsigned h2 = htanh2(hfma2(wh1s[5], s1h, hfma2(wh1s[4], s0h, S.hb16[2])));
            const unsigned h3 = htanh2(hfma2(wh1s[7], s1h, hfma2(wh1s[6], s0h, S.hb16[3])));
            unsigned zz = hfma2(wh2h[0], h0, bh2h);
            zz = hfma2(wh2h[1], h1, zz);
            zz = hfma2(wh2h[2], h2, zz);
            zz = hfma2(wh2h[3], h3, zz);
            const unsigned zh16 = htanh2(zz);
            float zl, zhf; cvt_f32p(zh16, zl, zhf);
            const u64 zf = pk2(zl, zhf);

            // eff: |z| > 0.01, counted exactly in f16x2
            S.eff16 = hadd2(S.eff16, hsetgt2(zh16 & 0x7FFF7FFFu, c001h));

            // robot MLP: exact f32x2 preacts (bias precision), f16x2 tanh
            const u64 rp0 = ffma2(wr1p[2], zf, ffma2(wr1p[1], S.s1, ffma2(wr1p[0], S.s0, br1p[0])));
            const u64 rp1 = ffma2(wr1p[5], zf, ffma2(wr1p[4], S.s1, ffma2(wr1p[3], S.s0, br1p[1])));
            const u64 rp2 = ffma2(wr1p[8], zf, ffma2(wr1p[7], S.s1, ffma2(wr1p[6], S.s0, br1p[2])));
            const unsigned r0 = htanh2(cvt_f16x2(rp0));
            const unsigned r1 = htanh2(cvt_f16x2(rp1));
            const unsigned r2 = htanh2(cvt_f16x2(rp2));

            unsigned as16 = hmul2(wr2h[0], r0);
            as16 = hfma2(wr2h[1], r1, as16);
            as16 = hfma2(wr2h[2], r2, as16);
            float al, ah; cvt_f32p(as16, al, ah);
            const u64 a = fadd2(pk2(al, ah), br2p);

            S.s0 = ffma2(cDT, S.s1, S.s0);
            S.s1 = ffma2(cDT, a, S.s1);

            const u64 d = fsub2(zt, zf);
            S.nor = ffma2(d, d, S.nor);
        };

        #pragma unroll 1
        for (int st = 0; st < NSTEPS - 1; st++) {
            body(P[0]);
            body(P[1]);
        }

        #pragma unroll
        for (int q = 0; q < 2; q++) {
            const u64 e0 = fsub2(P[q].t0, P[q].s0);
            const u64 e1 = fsub2(P[q].t1, P[q].s1);
            P[q].err0 = ffma2(e0, e0, P[q].err0);
            P[q].err1 = ffma2(e1, e1, P[q].err1);
            float a0, b0, a1, b1, nl, nh, el, eh;
            up2(P[q].err0, a0, b0); up2(P[q].err1, a1, b1); up2(P[q].nor, nl, nh);
            cvt_f32p(P[q].eff16, el, eh);
            csum += (fmaf(10.0f, a0, a1) + el) + (fmaf(10.0f, b0, b1) + eh);
            nsum += nl + nh;
        }
    }

    // ---- deterministic fused reduction ----
    #pragma unroll
    for (int off = 16; off > 0; off >>= 1) {
        csum += __shfl_down_sync(0xffffffffu, csum, off);
        nsum += __shfl_down_sync(0xffffffffu, nsum, off);
    }
    __shared__ float sc[TPB / 32], sn[TPB / 32];
    __shared__ int s_last;
    const int lane = threadIdx.x & 31;
    const int warp = threadIdx.x >> 5;
    if (lane == 0) { sc[warp] = csum; sn[warp] = nsum; }
    __syncthreads();
    if (threadIdx.x == 0) {
        float bc = 0.0f, bn = 0.0f;
        #pragma unroll
        for (int w = 0; w < TPB / 32; w++) { bc += sc[w]; bn += sn[w]; }
        g_partials[2 * blockIdx.x]     = bc;
        g_partials[2 * blockIdx.x + 1] = bn;
        __threadfence();
        unsigned t = atomicAdd(&g_count, 1u);
        s_last = (t == (unsigned)(nblocks - 1)) ? 1 : 0;
    }
    __syncthreads();

    if (s_last) {
        __threadfence();
        float c = 0.0f, n = 0.0f;
        for (int j = threadIdx.x; j < nblocks; j += TPB) {
            c += g_partials[2 * j];
            n += g_partials[2 * j + 1];
        }
        #pragma unroll
        for (int off = 16; off > 0; off >>= 1) {
            c += __shfl_down_sync(0xffffffffu, c, off);
            n += __shfl_down_sync(0xffffffffu, n, off);
        }
        if (lane == 0) { sc[warp] = c; sn[warp] = n; }
        __syncthreads();
        if (threadIdx.x == 0) {
            c = 0.0f; n = 0.0f;
            #pragma unroll
            for (int w = 0; w < TPB / 32; w++) { c += sc[w]; n += sn[w]; }
            const float invN = 1.0f / (float)N;
            out[0] = c * invN + alpha[0] * (n * invN);
            g_count = 0;  // reset for next graph replay
        }
    }
}

extern "C" void kernel_launch(void* const* d_in, const int* in_sizes, int n_in,
                              void* d_out, int out_size)
{
    const float* omega = (const float*)d_in[0];
    const float* Wh1   = (const float*)d_in[1];
    const float* bh1   = (const float*)d_in[2];
    const float* Wh2   = (const float*)d_in[3];
    const float* bh2   = (const float*)d_in[4];
    const float* Wr1   = (const float*)d_in[5];
    const float* br1   = (const float*)d_in[6];
    const float* Wr2   = (const float*)d_in[7];
    const float* br2   = (const float*)d_in[8];
    const float* alpha = (const float*)d_in[9];
    (void)n_in; (void)out_size;

    const int N = in_sizes[0] / 2;   // omega is [2, N]
    const int npairs = N / 2;
    const int half = npairs / 2;     // 2 pairs (4 tasks) per thread
    int nblocks = (half + TPB - 1) / TPB;
    if (nblocks > MAXB) nblocks = MAXB;

    conv_fused_kernel<<<nblocks, TPB>>>(omega, Wh1, bh1, Wh2, bh2,
                                        Wr1, br1, Wr2, br2, alpha,
                                        (float*)d_out, N, half, nblocks);
}

// round 8
// speedup vs baseline: 1.0484x; 1.0484x over previous
#include <cuda_runtime.h>

#define DT 0.05f
#define NSTEPS 41
#define TPB 128
#define MAXB 4096

typedef unsigned long long u64;

__device__ float g_partials[2 * MAXB];
__device__ unsigned g_count;

// ---------- f32x2 helpers ----------
static __device__ __forceinline__ u64 pk2(float lo, float hi) {
    u64 r; asm("mov.b64 %0, {%1, %2};" : "=l"(r) : "f"(lo), "f"(hi)); return r;
}
static __device__ __forceinline__ void up2(u64 v, float& lo, float& hi) {
    asm("mov.b64 {%0, %1}, %2;" : "=f"(lo), "=f"(hi) : "l"(v));
}
static __device__ __forceinline__ u64 bc2(float x) { return pk2(x, x); }
static __device__ __forceinline__ u64 ffma2(u64 a, u64 b, u64 c) {
    u64 d; asm("fma.rn.f32x2 %0, %1, %2, %3;" : "=l"(d) : "l"(a), "l"(b), "l"(c)); return d;
}
static __device__ __forceinline__ u64 fsub2(u64 a, u64 b) {
    u64 d; asm("sub.rn.f32x2 %0, %1, %2;" : "=l"(d) : "l"(a), "l"(b)); return d;
}
static __device__ __forceinline__ u64 fadd2(u64 a, u64 b) {
    u64 d; asm("add.rn.f32x2 %0, %1, %2;" : "=l"(d) : "l"(a), "l"(b)); return d;
}

// ---------- f16x2 helpers ----------
static __device__ __forceinline__ unsigned hfma2(unsigned a, unsigned b, unsigned c) {
    unsigned d; asm("fma.rn.f16x2 %0, %1, %2, %3;" : "=r"(d) : "r"(a), "r"(b), "r"(c)); return d;
}
static __device__ __forceinline__ unsigned hsub2(unsigned a, unsigned b) {
    unsigned d; asm("sub.rn.f16x2 %0, %1, %2;" : "=r"(d) : "r"(a), "r"(b)); return d;
}
static __device__ __forceinline__ unsigned hadd2(unsigned a, unsigned b) {
    unsigned d; asm("add.rn.f16x2 %0, %1, %2;" : "=r"(d) : "r"(a), "r"(b)); return d;
}
static __device__ __forceinline__ unsigned htanh2(unsigned x) {
    asm("tanh.approx.f16x2 %0, %0;" : "+r"(x)); return x;
}
static __device__ __forceinline__ unsigned hsetgt2(unsigned a, unsigned b) {
    unsigned d; asm("set.gt.f16x2.f16x2 %0, %1, %2;" : "=r"(d) : "r"(a), "r"(b)); return d;
}
static __device__ __forceinline__ unsigned bch(float x) {
    unsigned r; asm("cvt.rn.f16x2.f32 %0, %1, %1;" : "=r"(r) : "f"(x)); return r;
}
static __device__ __forceinline__ unsigned cvt_f16x2(u64 x) {           // XU op
    float lo, hi; up2(x, lo, hi);
    unsigned r; asm("cvt.rn.f16x2.f32 %0, %1, %2;" : "=r"(r) : "f"(hi), "f"(lo));
    return r;
}
static __device__ __forceinline__ void cvt_f32p(unsigned h, float& lo, float& hi) {  // 2 XU ops
    asm("{\n\t.reg .b16 l, hh;\n\tmov.b32 {l, hh}, %2;\n\t"
        "cvt.f32.f16 %0, l;\n\tcvt.f32.f16 %1, hh;\n\t}"
        : "=f"(lo), "=f"(hi) : "r"(h));
}

__global__ void __launch_bounds__(TPB, 6) conv_fused_kernel(
    const float* __restrict__ omega,
    const float* __restrict__ Wh1, const float* __restrict__ bh1,
    const float* __restrict__ Wh2, const float* __restrict__ bh2,
    const float* __restrict__ Wr1, const float* __restrict__ br1,
    const float* __restrict__ Wr2, const float* __restrict__ br2,
    const float* __restrict__ alpha, float* __restrict__ out,
    int N, int npairs, int nblocks)
{
    // ---- hoisted weights, f16x2 broadcast (feed HFMA2; no per-step converts) ----
    unsigned wh1s[8], wh2h[4], wr1h[9], br1h[3], wr2h[3];
    #pragma unroll
    for (int j = 0; j < 4; j++) {
        wh1s[2 * j + 0] = bch(__ldg(&Wh1[4 * j + 2]));   // s0 column
        wh1s[2 * j + 1] = bch(__ldg(&Wh1[4 * j + 3]));   // s1 column
        wh2h[j] = bch(__ldg(&Wh2[j]));
    }
    #pragma unroll
    for (int j = 0; j < 9; j++) wr1h[j] = bch(__ldg(&Wr1[j]));
    #pragma unroll
    for (int j = 0; j < 3; j++) { br1h[j] = bch(__ldg(&br1[j])); wr2h[j] = bch(__ldg(&Wr2[j])); }
    const unsigned bh2h  = bch(__ldg(&bh2[0]));
    const unsigned br2h  = bch(__ldg(&br2[0]));
    const unsigned dtH   = bch(DT);
    const unsigned cP1h  = bch(0.1f);
    const unsigned c001h = bch(0.01f);
    const u64 cDT = bc2(DT);

    float csum = 0.0f, nsum = 0.0f;

    for (int p = blockIdx.x * TPB + threadIdx.x; p < npairs; p += nblocks * TPB) {
        const float2 t0v = *(const float2*)(omega + 2 * p);
        const float2 t1v = *(const float2*)(omega + N + 2 * p);
        const u64 t0 = pk2(t0v.x, t0v.y);
        const u64 t1 = pk2(t1v.x, t1v.y);
        const unsigned t0h = cvt_f16x2(t0);
        const unsigned t1h = cvt_f16x2(t1);

        // prefold human layer-1 t-contributions (f32 exact, cvt once)
        unsigned hb16[4];
        #pragma unroll
        for (int j = 0; j < 4; j++) {
            u64 hb = ffma2(bc2(__ldg(&Wh1[4 * j + 1])), t1,
                    ffma2(bc2(__ldg(&Wh1[4 * j + 0])), t0,
                          bc2(__ldg(&bh1[j]))));
            hb16[j] = cvt_f16x2(hb);
        }

        u64 s0 = 0ull, s1 = 0ull, err0 = 0ull, err1 = 0ull, nor32 = 0ull;
        unsigned eff16 = 0u;
        unsigned s0h = 0u, s1h = 0u;

        #pragma unroll 1
        for (int w = 0; w < (NSTEPS - 1) / 4; w++) {
            // refresh shadow f16 state from exact f32 (bounds drift to <=3 f16 steps)
            s0h = cvt_f16x2(s0);
            s1h = cvt_f16x2(s1);
            unsigned norw = 0u;

            #pragma unroll
            for (int k = 0; k < 4; k++) {
                // exact f32 error accumulation (dominant cost term)
                const u64 e0 = fsub2(t0, s0);
                const u64 e1 = fsub2(t1, s1);
                err0 = ffma2(e0, e0, err0);            // x10 folded at the end
                err1 = ffma2(e1, e1, err1);

                // f16 zt from shadow state
                const unsigned e0h = hsub2(t0h, s0h);
                const unsigned e1h = hsub2(t1h, s1h);
                const unsigned zt16 = hfma2(cP1h, e1h, e0h);

                // human MLP (all f16)
                const unsigned h0 = htanh2(hfma2(wh1s[1], s1h, hfma2(wh1s[0], s0h, hb16[0])));
                const unsigned h1 = htanh2(hfma2(wh1s[3], s1h, hfma2(wh1s[2], s0h, hb16[1])));
                const unsigned h2 = htanh2(hfma2(wh1s[5], s1h, hfma2(wh1s[4], s0h, hb16[2])));
                const unsigned h3 = htanh2(hfma2(wh1s[7], s1h, hfma2(wh1s[6], s0h, hb16[3])));
                unsigned zz = hfma2(wh2h[0], h0, bh2h);
                zz = hfma2(wh2h[1], h1, zz);
                zz = hfma2(wh2h[2], h2, zz);
                const unsigned z16 = htanh2(hfma2(wh2h[3], h3, zz));

                // eff count (exact in f16: integers <= 40)
                eff16 = hadd2(eff16, hsetgt2(z16 & 0x7FFF7FFFu, c001h));

                // nor window accumulator (f16, small magnitude per window)
                const unsigned d16 = hsub2(zt16, z16);
                norw = hfma2(d16, d16, norw);

                // robot MLP (all f16)
                const unsigned q0 = htanh2(hfma2(wr1h[2], z16, hfma2(wr1h[1], s1h, hfma2(wr1h[0], s0h, br1h[0]))));
                const unsigned q1 = htanh2(hfma2(wr1h[5], z16, hfma2(wr1h[4], s1h, hfma2(wr1h[3], s0h, br1h[1]))));
                const unsigned q2 = htanh2(hfma2(wr1h[8], z16, hfma2(wr1h[7], s1h, hfma2(wr1h[6], s0h, br1h[2]))));
                unsigned a16 = hfma2(wr2h[0], q0, br2h);
                a16 = hfma2(wr2h[1], q1, a16);
                a16 = hfma2(wr2h[2], q2, a16);

                // a to f32 (the only per-step converts: 2 XU ops)
                float al, ah; cvt_f32p(a16, al, ah);
                const u64 a32 = pk2(al, ah);

                // state updates: exact f32 + shadow f16 (fma pipe only)
                s0 = ffma2(cDT, s1, s0);
                s1 = ffma2(cDT, a32, s1);
                s0h = hfma2(dtH, s1h, s0h);
                s1h = hfma2(dtH, a16, s1h);
            }

            // flush window nor to f32
            float nl, nh; cvt_f32p(norw, nl, nh);
            nor32 = fadd2(nor32, pk2(nl, nh));
        }

        // final error term
        const u64 e0 = fsub2(t0, s0);
        const u64 e1 = fsub2(t1, s1);
        err0 = ffma2(e0, e0, err0);
        err1 = ffma2(e1, e1, err1);

        float a0, b0, a1, b1, nl, nh, el, eh;
        up2(err0, a0, b0); up2(err1, a1, b1); up2(nor32, nl, nh);
        cvt_f32p(eff16, el, eh);
        csum += (fmaf(10.0f, a0, a1) + el) + (fmaf(10.0f, b0, b1) + eh);
        nsum += nl + nh;
    }

    // ---- deterministic fused reduction ----
    #pragma unroll
    for (int off = 16; off > 0; off >>= 1) {
        csum += __shfl_down_sync(0xffffffffu, csum, off);
        nsum += __shfl_down_sync(0xffffffffu, nsum, off);
    }
    __shared__ float sc[TPB / 32], sn[TPB / 32];
    __shared__ int s_last;
    const int lane = threadIdx.x & 31;
    const int warp = threadIdx.x >> 5;
    if (lane == 0) { sc[warp] = csum; sn[warp] = nsum; }
    __syncthreads();
    if (threadIdx.x == 0) {
        float bc = 0.0f, bn = 0.0f;
        #pragma unroll
        for (int w = 0; w < TPB / 32; w++) { bc += sc[w]; bn += sn[w]; }
        g_partials[2 * blockIdx.x]     = bc;
        g_partials[2 * blockIdx.x + 1] = bn;
        __threadfence();
        unsigned t = atomicAdd(&g_count, 1u);
        s_last = (t == (unsigned)(nblocks - 1)) ? 1 : 0;
    }
    __syncthreads();

    if (s_last) {
        __threadfence();
        float c = 0.0f, n = 0.0f;
        for (int j = threadIdx.x; j < nblocks; j += TPB) {
            c += g_partials[2 * j];
            n += g_partials[2 * j + 1];
        }
        #pragma unroll
        for (int off = 16; off > 0; off >>= 1) {
            c += __shfl_down_sync(0xffffffffu, c, off);
            n += __shfl_down_sync(0xffffffffu, n, off);
        }
        if (lane == 0) { sc[warp] = c; sn[warp] = n; }
        __syncthreads();
        if (threadIdx.x == 0) {
            c = 0.0f; n = 0.0f;
            #pragma unroll
            for (int w = 0; w < TPB / 32; w++) { c += sc[w]; n += sn[w]; }
            const float invN = 1.0f / (float)N;
            out[0] = c * invN + alpha[0] * (n * invN);
            g_count = 0;  // reset for next graph replay
        }
    }
}

extern "C" void kernel_launch(void* const* d_in, const int* in_sizes, int n_in,
                              void* d_out, int out_size)
{
    const float* omega = (const float*)d_in[0];
    const float* Wh1   = (const float*)d_in[1];
    const float* bh1   = (const float*)d_in[2];
    const float* Wh2   = (const float*)d_in[3];
    const float* bh2   = (const float*)d_in[4];
    const float* Wr1   = (const float*)d_in[5];
    const float* br1   = (const float*)d_in[6];
    const float* Wr2   = (const float*)d_in[7];
    const float* br2   = (const float*)d_in[8];
    const float* alpha = (const float*)d_in[9];
    (void)n_in; (void)out_size;

    const int N = in_sizes[0] / 2;   // omega is [2, N]
    const int npairs = N / 2;
    int nblocks = (npairs + TPB - 1) / TPB;
    if (nblocks > MAXB) nblocks = MAXB;

    conv_fused_kernel<<<nblocks, TPB>>>(omega, Wh1, bh1, Wh2, bh2,
                                        Wr1, br1, Wr2, br2, alpha,
                                        (float*)d_out, N, npairs, nblocks);
}